// round 6
// baseline (speedup 1.0000x reference)
#include <cuda_runtime.h>

// x is [B=8, S=4096, D=1024] fp32; out[b,s,d] = x[b,s,d] + PE[s,d].
// PE[s,d] = sin(s / 10000^(j/1024)) for even d (j=d), cos(...) for odd d (j=d-1).
#define PE_S 4096
#define PE_D 1024
#define PE_B 8
#define ROWS_PER_BLOCK 16
#define CHUNK 4
#define F4_PER_ROW (PE_D / 4)                 // 256

// grid = (4096/16 row-groups) x (8 batches) = 2048 blocks, 256 threads.
// Each block covers one batch x 16 consecutive rows = one contiguous 64KB
// read stream + one contiguous 64KB write stream.
#define GRID_BLOCKS ((PE_S / ROWS_PER_BLOCK) * PE_B)

// Accurate base sincos: reduce fp32 angle mod 2pi in double, sinf/cosf on the
// small remainder (safe under --use_fast_math). Used once per thread.
__device__ __forceinline__ void acc_sincos(float angle, float& s_out, float& c_out) {
    double a = (double)angle;
    double k = rint(a * 0.15915494309189535);          // 1/(2*pi)
    float r = (float)(a - k * 6.283185307179586);      // |r| <= pi
    s_out = sinf(r);
    c_out = cosf(r);
}

__global__ void __launch_bounds__(256)
pe_add_kernel(const float4* __restrict__ x, float4* __restrict__ out) {
    // blockIdx.x = b * 256 + rg
    int b  = blockIdx.x >> 8;                  // batch 0..7
    int rg = blockIdx.x & 255;                 // row group 0..255
    int s0 = rg << 4;                          // first of 16 consecutive rows
    int c  = threadIdx.x;                      // float4 column index 0..255

    // Frequencies for columns 4c..4c+3:
    //   pair 0: p0 = 10000^(4c/1024) = 2^(c*K),  pair 1: p1 = 2^(c*K + C)
    const float K = 0.051905126482615075f;     // log2(10000)/256
    const float C = 0.025952563241307537f;     // log2(10000)/512
    float fc = (float)c;
    float p0 = exp2f(fc * K);
    float p1 = exp2f(fmaf(fc, K, C));

    // Base PE at row s0 (accurate), matching reference fp32 s/p division.
    float fs = (float)s0;
    float sn0, cs0, sn1, cs1;
    acc_sincos(fs / p0, sn0, cs0);
    acc_sincos(fs / p1, sn1, cs1);

    // Per-row angle increments delta = 1/p (<= 1 rad, no reduction needed).
    float d0 = 1.0f / p0, d1 = 1.0f / p1;
    float cw0 = cosf(d0), sw0 = sinf(d0);
    float cw1 = cosf(d1), sw1 = sinf(d1);

    size_t base = ((size_t)b * PE_S + s0) * F4_PER_ROW + c;

    // Process 16 rows in chunks of 4: load 4 (MLP=4), add+store 4 with the
    // rotation recurrence between rows. Staging = 16 regs instead of 64.
#pragma unroll
    for (int g = 0; g < ROWS_PER_BLOCK; g += CHUNK) {
        float4 v[CHUNK];
#pragma unroll
        for (int i = 0; i < CHUNK; i++) {
            v[i] = __ldcs(&x[base + (size_t)(g + i) * F4_PER_ROW]);
        }
#pragma unroll
        for (int i = 0; i < CHUNK; i++) {
            float4 o;
            o.x = v[i].x + sn0;   // even col -> sin
            o.y = v[i].y + cs0;   // odd col  -> cos
            o.z = v[i].z + sn1;
            o.w = v[i].w + cs1;
            __stcs(&out[base + (size_t)(g + i) * F4_PER_ROW], o);

            // sin(a+d) = sin a * cos d + cos a * sin d
            // cos(a+d) = cos a * cos d - sin a * sin d
            float ns0 = fmaf(sn0, cw0,  cs0 * sw0);
            float nc0 = fmaf(cs0, cw0, -sn0 * sw0);
            float ns1 = fmaf(sn1, cw1,  cs1 * sw1);
            float nc1 = fmaf(cs1, cw1, -sn1 * sw1);
            sn0 = ns0; cs0 = nc0; sn1 = ns1; cs1 = nc1;
        }
    }
}

extern "C" void kernel_launch(void* const* d_in, const int* in_sizes, int n_in,
                              void* d_out, int out_size) {
    (void)in_sizes; (void)n_in; (void)out_size;
    const float4* x = (const float4*)d_in[0];
    float4* out = (float4*)d_out;

    pe_add_kernel<<<GRID_BLOCKS, 256>>>(x, out);
}

// round 7
// speedup vs baseline: 1.0339x; 1.0339x over previous
#include <cuda_runtime.h>

// x is [B=8, S=4096, D=1024] fp32; out[b,s,d] = x[b,s,d] + PE[s,d].
// PE[s,d] = sin(s / 10000^(j/1024)) for even d (j=d), cos(...) for odd d (j=d-1).
#define PE_S 4096
#define PE_D 1024
#define PE_B 8
#define ROWS_PER_BLOCK 16
#define CHUNK 8
#define F4_PER_ROW (PE_D / 4)                 // 256

// grid = (4096/16 row-groups) x (8 batches) = 2048 blocks, 256 threads.
// Each block covers one batch x 16 consecutive rows = one contiguous 64KB
// read stream + one contiguous 64KB write stream, processed as two
// MLP=8 chunks (R5/R6 established MLP=8 > occupancy as the binding factor).
#define GRID_BLOCKS ((PE_S / ROWS_PER_BLOCK) * PE_B)

// Accurate base sincos: reduce fp32 angle mod 2pi in double, sinf/cosf on the
// small remainder (safe under --use_fast_math). Used once per thread.
__device__ __forceinline__ void acc_sincos(float angle, float& s_out, float& c_out) {
    double a = (double)angle;
    double k = rint(a * 0.15915494309189535);          // 1/(2*pi)
    float r = (float)(a - k * 6.283185307179586);      // |r| <= pi
    s_out = sinf(r);
    c_out = cosf(r);
}

__global__ void __launch_bounds__(256)
pe_add_kernel(const float4* __restrict__ x, float4* __restrict__ out) {
    // blockIdx.x = b * 256 + rg
    int b  = blockIdx.x >> 8;                  // batch 0..7
    int rg = blockIdx.x & 255;                 // row group 0..255
    int s0 = rg << 4;                          // first of 16 consecutive rows
    int c  = threadIdx.x;                      // float4 column index 0..255

    // Frequencies for columns 4c..4c+3:
    //   pair 0: p0 = 10000^(4c/1024) = 2^(c*K),  pair 1: p1 = 2^(c*K + C)
    const float K = 0.051905126482615075f;     // log2(10000)/256
    const float C = 0.025952563241307537f;     // log2(10000)/512
    float fc = (float)c;
    float p0 = exp2f(fc * K);
    float p1 = exp2f(fmaf(fc, K, C));

    // Base PE at row s0 (accurate), matching reference fp32 s/p division.
    float fs = (float)s0;
    float sn0, cs0, sn1, cs1;
    acc_sincos(fs / p0, sn0, cs0);
    acc_sincos(fs / p1, sn1, cs1);

    // Per-row angle increments delta = 1/p (<= 1 rad, no reduction needed).
    float d0 = 1.0f / p0, d1 = 1.0f / p1;
    float cw0 = cosf(d0), sw0 = sinf(d0);
    float cw1 = cosf(d1), sw1 = sinf(d1);

    size_t base = ((size_t)b * PE_S + s0) * F4_PER_ROW + c;

    // Two chunks of 8 rows: front-batch 8 loads (MLP=8), then add+store with
    // the rotation recurrence between rows.
#pragma unroll
    for (int g = 0; g < ROWS_PER_BLOCK; g += CHUNK) {
        float4 v[CHUNK];
#pragma unroll
        for (int i = 0; i < CHUNK; i++) {
            v[i] = __ldcs(&x[base + (size_t)(g + i) * F4_PER_ROW]);
        }
#pragma unroll
        for (int i = 0; i < CHUNK; i++) {
            float4 o;
            o.x = v[i].x + sn0;   // even col -> sin
            o.y = v[i].y + cs0;   // odd col  -> cos
            o.z = v[i].z + sn1;
            o.w = v[i].w + cs1;
            __stcs(&out[base + (size_t)(g + i) * F4_PER_ROW], o);

            // sin(a+d) = sin a cos d + cos a sin d
            // cos(a+d) = cos a cos d - sin a sin d
            float ns0 = fmaf(sn0, cw0,  cs0 * sw0);
            float nc0 = fmaf(cs0, cw0, -sn0 * sw0);
            float ns1 = fmaf(sn1, cw1,  cs1 * sw1);
            float nc1 = fmaf(cs1, cw1, -sn1 * sw1);
            sn0 = ns0; cs0 = nc0; sn1 = ns1; cs1 = nc1;
        }
    }
}

extern "C" void kernel_launch(void* const* d_in, const int* in_sizes, int n_in,
                              void* d_out, int out_size) {
    (void)in_sizes; (void)n_in; (void)out_size;
    const float4* x = (const float4*)d_in[0];
    float4* out = (float4*)d_out;

    pe_add_kernel<<<GRID_BLOCKS, 256>>>(x, out);
}

// round 9
// speedup vs baseline: 1.0678x; 1.0329x over previous
#include <cuda_runtime.h>

// x is [B=8, S=4096, D=1024] fp32; out[b,s,d] = x[b,s,d] + PE[s,d].
// PE[s,d] = sin(s / 10000^(j/1024)) for even d (j=d), cos(...) for odd d (j=d-1).
//
// Final kernel (R5 shape — best of 6 measured variants at 38.50us kernel,
// 6.97 TB/s app throughput = ~87% of HBM spec):
//  - single fused launch, PE computed in-kernel (exp2f powers)
//  - block = one batch x 8 consecutive rows -> contiguous 32KB rd + 32KB wr
//  - one accurate double-reduced sincos per thread, rotated across 8 rows
//  - 8 front-batched LDG.128 (MLP=8) then 8 STG.128, both with .cs hints
#define PE_S 4096
#define PE_D 1024
#define PE_B 8
#define ROWS_PER_BLOCK 8
#define F4_PER_ROW (PE_D / 4)                 // 256
#define GRID_BLOCKS ((PE_S / ROWS_PER_BLOCK) * PE_B)   // 4096

// Accurate base sincos: reduce fp32 angle mod 2pi in double, sinf/cosf on the
// small remainder (safe under --use_fast_math). Used once per thread.
__device__ __forceinline__ void acc_sincos(float angle, float& s_out, float& c_out) {
    double a = (double)angle;
    double k = rint(a * 0.15915494309189535);          // 1/(2*pi)
    float r = (float)(a - k * 6.283185307179586);      // |r| <= pi
    s_out = sinf(r);
    c_out = cosf(r);
}

__global__ void __launch_bounds__(256)
pe_add_kernel(const float4* __restrict__ x, float4* __restrict__ out) {
    // blockIdx.x = b * 512 + rg
    int b  = blockIdx.x >> 9;                  // batch 0..7
    int rg = blockIdx.x & 511;                 // row group 0..511
    int s0 = rg << 3;                          // first of 8 consecutive rows
    int c  = threadIdx.x;                      // float4 column index 0..255

    // Frequencies for columns 4c..4c+3:
    //   pair 0: p0 = 10000^(4c/1024) = 2^(c*K),  pair 1: p1 = 2^(c*K + C)
    const float K = 0.051905126482615075f;     // log2(10000)/256
    const float C = 0.025952563241307537f;     // log2(10000)/512
    float fc = (float)c;
    float p0 = exp2f(fc * K);
    float p1 = exp2f(fmaf(fc, K, C));

    // Base PE at row s0 (accurate), matching reference fp32 s/p division.
    float fs = (float)s0;
    float sn0, cs0, sn1, cs1;
    acc_sincos(fs / p0, sn0, cs0);
    acc_sincos(fs / p1, sn1, cs1);

    // Per-row angle increments delta = 1/p (<= 1 rad, no reduction needed).
    float d0 = 1.0f / p0, d1 = 1.0f / p1;
    float cw0 = cosf(d0), sw0 = sinf(d0);
    float cw1 = cosf(d1), sw1 = sinf(d1);

    // Front-batch all 8 row loads: contiguous 32KB per block (MLP=8/thread).
    size_t base = ((size_t)b * PE_S + s0) * F4_PER_ROW + c;
    float4 v[ROWS_PER_BLOCK];
#pragma unroll
    for (int i = 0; i < ROWS_PER_BLOCK; i++) {
        v[i] = __ldcs(&x[base + (size_t)i * F4_PER_ROW]);
    }

    // Add PE and store; rotate (sn,cs) by delta between rows.
#pragma unroll
    for (int i = 0; i < ROWS_PER_BLOCK; i++) {
        float4 o;
        o.x = v[i].x + sn0;   // even col -> sin
        o.y = v[i].y + cs0;   // odd col  -> cos
        o.z = v[i].z + sn1;
        o.w = v[i].w + cs1;
        __stcs(&out[base + (size_t)i * F4_PER_ROW], o);

        // sin(a+d) = sin a * cos d + cos a * sin d
        // cos(a+d) = cos a * cos d - sin a * sin d
        float ns0 = fmaf(sn0, cw0,  cs0 * sw0);
        float nc0 = fmaf(cs0, cw0, -sn0 * sw0);
        float ns1 = fmaf(sn1, cw1,  cs1 * sw1);
        float nc1 = fmaf(cs1, cw1, -sn1 * sw1);
        sn0 = ns0; cs0 = nc0; sn1 = ns1; cs1 = nc1;
    }
}

extern "C" void kernel_launch(void* const* d_in, const int* in_sizes, int n_in,
                              void* d_out, int out_size) {
    (void)in_sizes; (void)n_in; (void)out_size;
    const float4* x = (const float4*)d_in[0];
    float4* out = (float4*)d_out;

    pe_add_kernel<<<GRID_BLOCKS, 256>>>(x, out);
}